// round 4
// baseline (speedup 1.0000x reference)
#include <cuda_runtime.h>
#include <cstdint>

#define NN 100000
#define EE 800000
#define HH 4
#define FF 64
#define KTOT 320          // 4*64 (attention heads) + 64 (global branch)
#define SCAN_B 98         // ceil(100000/1024)

// ---------------- device scratch (static: no runtime allocation) -------------
__device__ __align__(16) float g_wsrc[HH*FF];
__device__ __align__(16) float g_wdst[HH*FF];
__device__ __align__(16) float g_Mall[KTOT*FF];   // combined projection [k][o]
__device__ __align__(16) float g_bias[FF];
__device__ __align__(16) float4 g_ssrc4[NN];
__device__ __align__(16) float4 g_sdst4[NN];
__device__ int   g_is64;
__device__ int   g_eidx[2*EE];    // decoded edge indices: [src row | dst row]
__device__ int   g_cnt[NN];
__device__ int   g_rowptr[NN+1];
__device__ int   g_cursor[NN];
__device__ int   g_bsum[SCAN_B];
__device__ float g_deg[NN];
__device__ int   g_esrc[EE];
__device__ __align__(16) float4 g_escore[EE];
__device__ __align__(16) float g_A[(size_t)NN*KTOT];  // [N][320]: agg heads | g2
__device__ __align__(16) float g_g1[(size_t)NN*FF];

// ---------------- helpers ----------------------------------------------------
__device__ __forceinline__ float wredmax(float v){
#pragma unroll
    for (int o = 16; o > 0; o >>= 1) v = fmaxf(v, __shfl_xor_sync(0xffffffffu, v, o));
    return v;
}
__device__ __forceinline__ float wredsum(float v){
#pragma unroll
    for (int o = 16; o > 0; o >>= 1) v += __shfl_xor_sync(0xffffffffu, v, o);
    return v;
}
__device__ __forceinline__ float lrelu(float v){ return v > 0.f ? v : 0.2f * v; }

// ---------------- K-1a: detect int32 vs int64 edge_index ---------------------
// For int64 node ids < 2^31, every odd 32-bit word is 0. For an int32 buffer,
// odd words are random node ids -> essentially never all zero.
__global__ void k_detect(const int* __restrict__ ei32){
    int t = threadIdx.x;                  // 0..31
    int v = ei32[2*t + 1];
    unsigned any = __ballot_sync(0xffffffffu, v != 0);
    if (t == 0) g_is64 = (any == 0u) ? 1 : 0;
}

// ---------------- K-1b: decode + clamp indices into g_eidx -------------------
__global__ void k_decode(const void* __restrict__ ei){
    int e = blockIdx.x*blockDim.x + threadIdx.x;
    if (e >= 2*EE) return;
    int v;
    if (g_is64) v = (int)((const long long*)ei)[e];
    else        v = ((const int*)ei)[e];
    v = (v < 0) ? 0 : (v >= NN ? NN-1 : v);   // defensive clamp
    g_eidx[e] = v;
}

// ---------------- K0a: w_src/w_dst = W_att[h] @ a_{src,dst}[h] ---------------
__global__ void k_wvec(const float* __restrict__ W_att,
                       const float* __restrict__ a_src,
                       const float* __restrict__ a_dst){
    int b = blockIdx.x;           // 0..7
    int h = b >> 1, sel = b & 1;
    int i = threadIdx.x;          // 0..63
    const float* W = W_att + (size_t)h*FF*FF + (size_t)i*FF;
    const float* a = (sel ? a_dst : a_src) + h*FF;
    float s = 0.f;
#pragma unroll 8
    for (int o = 0; o < FF; o++) s += W[o]*a[o];
    (sel ? g_wdst : g_wsrc)[h*FF + i] = s;
}

// ---------------- K0b: Mall rows + bias --------------------------------------
__global__ void k_mall(const float* __restrict__ W_att,
                       const float* __restrict__ W_g,
                       const float* __restrict__ W_w,
                       const float* __restrict__ b_g,
                       const float* __restrict__ b_w){
    int r = blockIdx.x;   // 0..320 (320 == bias row)
    int o = threadIdx.x;  // 0..63
    if (r < 256) {
        int h = r >> 6, i = r & 63;
        const float* wa = W_att + (size_t)h*FF*FF + (size_t)i*FF;
        float s = 0.f;
#pragma unroll 8
        for (int j = 0; j < FF; j++) s += wa[j] * W_w[(size_t)j*FF + o];
        g_Mall[(size_t)r*FF + o] = 0.25f * s;
    } else if (r < 320) {
        int i = r - 256;
        float s = 0.f;
#pragma unroll 8
        for (int j = 0; j < FF; j++) s += W_g[(size_t)i*FF + j] * W_w[(size_t)(FF+j)*FF + o];
        g_Mall[(size_t)r*FF + o] = s;
    } else {
        float s = b_w[o];
#pragma unroll 8
        for (int j = 0; j < FF; j++) s += b_g[j] * W_w[(size_t)(FF+j)*FF + o];
        g_bias[o] = s;
    }
}

// ---------------- K1: per-node attention logits s_src/s_dst ------------------
__global__ void k_score(const float* __restrict__ x){
    int warp = threadIdx.x >> 5, lane = threadIdx.x & 31;
    int n = blockIdx.x*8 + warp;
    if (n >= NN) return;
    float2 xv = *(const float2*)(x + (size_t)n*FF + lane*2);
    float p[8];
#pragma unroll
    for (int h = 0; h < 4; h++) {
        float2 w = *(const float2*)(g_wsrc + h*FF + lane*2);
        p[h] = xv.x*w.x + xv.y*w.y;
    }
#pragma unroll
    for (int h = 0; h < 4; h++) {
        float2 w = *(const float2*)(g_wdst + h*FF + lane*2);
        p[4+h] = xv.x*w.x + xv.y*w.y;
    }
#pragma unroll
    for (int k = 0; k < 8; k++) p[k] = wredsum(p[k]);
    if (lane == 0) {
        g_ssrc4[n] = make_float4(p[0], p[1], p[2], p[3]);
        g_sdst4[n] = make_float4(p[4], p[5], p[6], p[7]);
    }
}

// ---------------- K2: zero histogram -----------------------------------------
__global__ void k_zero(){
    int i = blockIdx.x*blockDim.x + threadIdx.x;
    if (i < NN) g_cnt[i] = 0;
}

// ---------------- K3: dst histogram ------------------------------------------
__global__ void k_hist(){
    int e = blockIdx.x*blockDim.x + threadIdx.x;
    if (e < EE) atomicAdd(&g_cnt[g_eidx[EE + e]], 1);
}

// ---------------- K4: scan (3 stages) ----------------------------------------
__global__ void k_scan1(){
    __shared__ int sh[1024];
    int t = threadIdx.x;
    int i = blockIdx.x*1024 + t;
    int v = (i < NN) ? g_cnt[i] : 0;
    sh[t] = v; __syncthreads();
#pragma unroll
    for (int off = 1; off < 1024; off <<= 1) {
        int u = (t >= off) ? sh[t - off] : 0;
        __syncthreads();
        sh[t] += u;
        __syncthreads();
    }
    if (i < NN) g_rowptr[i+1] = sh[t];
    if (t == 1023) g_bsum[blockIdx.x] = sh[1023];
}
__global__ void k_scan2(){
    int run = 0;
    for (int b = 0; b < SCAN_B; b++) { int t = g_bsum[b]; g_bsum[b] = run; run += t; }
}
__global__ void k_scan3(){
    int t = threadIdx.x;
    int i = blockIdx.x*1024 + t;
    if (i < NN) {
        int incl = g_rowptr[i+1] + g_bsum[blockIdx.x];
        g_rowptr[i+1] = incl;
        int c = g_cnt[i];
        g_cursor[i] = incl - c;
        g_deg[i] = (float)(c > 0 ? c : 1);
        if (i == 0) g_rowptr[0] = 0;
    }
}

// ---------------- K5: scatter edges into CSR, with precomputed scores --------
__global__ void k_scatter(){
    int e = blockIdx.x*blockDim.x + threadIdx.x;
    if (e >= EE) return;
    int s = g_eidx[e];
    int d = g_eidx[EE + e];
    int p = atomicAdd(&g_cursor[d], 1);
    g_esrc[p] = s;
    float4 a = g_ssrc4[s];
    float4 b = g_sdst4[d];
    float4 sc;
    sc.x = lrelu(a.x + b.x); sc.y = lrelu(a.y + b.y);
    sc.z = lrelu(a.z + b.z); sc.w = lrelu(a.w + b.w);
    g_escore[p] = sc;
}

// ---------------- K6: segment softmax + weighted aggregate + hop-1 -----------
__global__ void k_att(const float* __restrict__ x){
    int warp = threadIdx.x >> 5, lane = threadIdx.x & 31;
    int n = blockIdx.x*8 + warp;
    if (n >= NN) return;
    int beg = g_rowptr[n], end = g_rowptr[n+1];
    size_t arow = (size_t)n*KTOT;
    if (beg == end) {
        float2 z = make_float2(0.f, 0.f);
#pragma unroll
        for (int h = 0; h < 4; h++) *(float2*)(g_A + arow + h*FF + lane*2) = z;
        *(float2*)(g_g1 + (size_t)n*FF + lane*2) = z;
        return;
    }
    const float NEG = -1e30f;
    float4 mx = make_float4(NEG, NEG, NEG, NEG);
    for (int j = beg + lane; j < end; j += 32) {
        float4 s = g_escore[j];
        mx.x = fmaxf(mx.x, s.x); mx.y = fmaxf(mx.y, s.y);
        mx.z = fmaxf(mx.z, s.z); mx.w = fmaxf(mx.w, s.w);
    }
    mx.x = wredmax(mx.x); mx.y = wredmax(mx.y);
    mx.z = wredmax(mx.z); mx.w = wredmax(mx.w);
    float4 den = make_float4(0.f, 0.f, 0.f, 0.f);
    for (int j = beg + lane; j < end; j += 32) {
        float4 s = g_escore[j];
        float4 e;
        e.x = __expf(s.x - mx.x); e.y = __expf(s.y - mx.y);
        e.z = __expf(s.z - mx.z); e.w = __expf(s.w - mx.w);
        den.x += e.x; den.y += e.y; den.z += e.z; den.w += e.w;
        g_escore[j] = e;
    }
    den.x = wredsum(den.x); den.y = wredsum(den.y);
    den.z = wredsum(den.z); den.w = wredsum(den.w);
    __syncwarp();
    float4 inv;
    inv.x = 1.f/fmaxf(den.x, 1e-16f); inv.y = 1.f/fmaxf(den.y, 1e-16f);
    inv.z = 1.f/fmaxf(den.z, 1e-16f); inv.w = 1.f/fmaxf(den.w, 1e-16f);

    float2 a0 = make_float2(0,0), a1 = a0, a2 = a0, a3 = a0, ag = a0;
    for (int j = beg; j < end; j++) {
        int s = g_esrc[j];              // uniform across warp -> broadcast
        float4 al = g_escore[j];        // uniform across warp
        float2 v = *(const float2*)(x + (size_t)s*FF + lane*2);
        a0.x += al.x*v.x; a0.y += al.x*v.y;
        a1.x += al.y*v.x; a1.y += al.y*v.y;
        a2.x += al.z*v.x; a2.y += al.z*v.y;
        a3.x += al.w*v.x; a3.y += al.w*v.y;
        ag.x += v.x;      ag.y += v.y;
    }
    *(float2*)(g_A + arow + 0*FF + lane*2) = make_float2(a0.x*inv.x, a0.y*inv.x);
    *(float2*)(g_A + arow + 1*FF + lane*2) = make_float2(a1.x*inv.y, a1.y*inv.y);
    *(float2*)(g_A + arow + 2*FF + lane*2) = make_float2(a2.x*inv.z, a2.y*inv.z);
    *(float2*)(g_A + arow + 3*FF + lane*2) = make_float2(a3.x*inv.w, a3.y*inv.w);
    float dinv = 1.f / g_deg[n];
    *(float2*)(g_g1 + (size_t)n*FF + lane*2) = make_float2(ag.x*dinv, ag.y*dinv);
}

// ---------------- K7: hop-2 mean aggregation into A cols 256..319 ------------
__global__ void k_hop2(){
    int warp = threadIdx.x >> 5, lane = threadIdx.x & 31;
    int n = blockIdx.x*8 + warp;
    if (n >= NN) return;
    int beg = g_rowptr[n], end = g_rowptr[n+1];
    float2 ag = make_float2(0.f, 0.f);
    for (int j = beg; j < end; j++) {
        int s = g_esrc[j];
        float2 v = *(const float2*)(g_g1 + (size_t)s*FF + lane*2);
        ag.x += v.x; ag.y += v.y;
    }
    float dinv = 1.f / g_deg[n];
    *(float2*)(g_A + (size_t)n*KTOT + 256 + lane*2) = make_float2(ag.x*dinv, ag.y*dinv);
}

// ---------------- K8: out = A[N,320] @ Mall[320,64] + bias  (fp32 FMA) -------
// Block tile: 128 rows x 64 cols, 128 threads, 8x8 per-thread tile.
// K staged 16 at a time: As transposed [k][m] (pad 132), Bs [k][n] (pad 68).
__global__ __launch_bounds__(128) void k_gemm(float* __restrict__ out){
    __shared__ float As[16][132];
    __shared__ float Bs[16][68];
    int t = threadIdx.x;
    int tx = t & 7;                 // col group: 8 groups x 8 cols
    int ty = t >> 3;                // row group: 16 groups x 8 rows
    int blockRow = blockIdx.x * 128;

    float acc[8][8];
#pragma unroll
    for (int i = 0; i < 8; i++)
#pragma unroll
        for (int j = 0; j < 8; j++) acc[i][j] = 0.f;

    int arow_l = t >> 2;            // 0..31
    int akc_l  = (t & 3) * 4;      // 0,4,8,12
    int brow_l = t >> 4;            // 0..7
    int bnc_l  = (t & 15) * 4;     // 0..60

    for (int kb = 0; kb < KTOT; kb += 16) {
#pragma unroll
        for (int p = 0; p < 4; p++) {
            int r = arow_l + p*32;
            int gr = blockRow + r;
            float4 v = make_float4(0.f, 0.f, 0.f, 0.f);
            if (gr < NN) v = *(const float4*)(g_A + (size_t)gr*KTOT + kb + akc_l);
            As[akc_l    ][r] = v.x;
            As[akc_l + 1][r] = v.y;
            As[akc_l + 2][r] = v.z;
            As[akc_l + 3][r] = v.w;
        }
#pragma unroll
        for (int p = 0; p < 2; p++) {
            int kr = brow_l + p*8;
            float4 v = *(const float4*)(g_Mall + (size_t)(kb + kr)*FF + bnc_l);
            *(float4*)&Bs[kr][bnc_l] = v;
        }
        __syncthreads();
#pragma unroll
        for (int k = 0; k < 16; k++) {
            float4 a0 = *(float4*)&As[k][ty*8];
            float4 a1 = *(float4*)&As[k][ty*8 + 4];
            float4 b0 = *(float4*)&Bs[k][tx*8];
            float4 b1 = *(float4*)&Bs[k][tx*8 + 4];
            float av[8] = {a0.x, a0.y, a0.z, a0.w, a1.x, a1.y, a1.z, a1.w};
            float bv[8] = {b0.x, b0.y, b0.z, b0.w, b1.x, b1.y, b1.z, b1.w};
#pragma unroll
            for (int i = 0; i < 8; i++)
#pragma unroll
                for (int j = 0; j < 8; j++) acc[i][j] += av[i] * bv[j];
        }
        __syncthreads();
    }
    float bsv[8];
#pragma unroll
    for (int j = 0; j < 8; j++) bsv[j] = g_bias[tx*8 + j];
#pragma unroll
    for (int i = 0; i < 8; i++) {
        int gr = blockRow + ty*8 + i;
        if (gr < NN) {
            float4 o0 = make_float4(acc[i][0]+bsv[0], acc[i][1]+bsv[1],
                                    acc[i][2]+bsv[2], acc[i][3]+bsv[3]);
            float4 o1 = make_float4(acc[i][4]+bsv[4], acc[i][5]+bsv[5],
                                    acc[i][6]+bsv[6], acc[i][7]+bsv[7]);
            *(float4*)(out + (size_t)gr*FF + tx*8)     = o0;
            *(float4*)(out + (size_t)gr*FF + tx*8 + 4) = o1;
        }
    }
}

// ---------------- launch ------------------------------------------------------
extern "C" void kernel_launch(void* const* d_in, const int* in_sizes, int n_in,
                              void* d_out, int out_size){
    const float* x     = (const float*)d_in[0];
    const void*  ei    = d_in[1];
    const float* W_att = (const float*)d_in[2];
    const float* a_src = (const float*)d_in[3];
    const float* a_dst = (const float*)d_in[4];
    const float* W_g   = (const float*)d_in[5];
    const float* b_g   = (const float*)d_in[6];
    const float* W_w   = (const float*)d_in[7];
    const float* b_w   = (const float*)d_in[8];
    float* out = (float*)d_out;

    k_detect <<<1, 32>>>((const int*)ei);
    k_decode <<<(2*EE + 255)/256, 256>>>(ei);
    k_wvec   <<<8, 64>>>(W_att, a_src, a_dst);
    k_mall   <<<321, 64>>>(W_att, W_g, W_w, b_g, b_w);
    k_score  <<<(NN + 7)/8, 256>>>(x);
    k_zero   <<<(NN + 255)/256, 256>>>();
    k_hist   <<<(EE + 255)/256, 256>>>();
    k_scan1  <<<SCAN_B, 1024>>>();
    k_scan2  <<<1, 1>>>();
    k_scan3  <<<SCAN_B, 1024>>>();
    k_scatter<<<(EE + 255)/256, 256>>>();
    k_att    <<<(NN + 7)/8, 256>>>(x);
    k_hop2   <<<(NN + 7)/8, 256>>>();
    k_gemm   <<<(NN + 127)/128, 128>>>(out);
}